// round 15
// baseline (speedup 1.0000x reference)
#include <cuda_runtime.h>
#include <cuda_fp16.h>
#include <cstdint>
#include <cstddef>

// ---------------------------------------------------------------------------
// Problem constants: B=8, N=M=128, H=512, D=2H=1024
// ---------------------------------------------------------------------------
#define BB   8
#define NN   128
#define HH   512
#define DD   1024

// Float scratch (scores + agg + w1v)
#define SZ_S    (BB*NN*NN)
#define SZ_SD   (BB*NN*2*NN)
#define SZ_AGG  (BB*NN*2*DD)
#define OFF_SC  0
#define OFF_SB  (OFF_SC + SZ_S)
#define OFF_SMN (OFF_SB + SZ_S)
#define OFF_SD1 (OFF_SMN + SZ_S)
#define OFF_SD2 (OFF_SD1 + SZ_SD)
#define OFF_AGG (OFF_SD2 + SZ_SD)
#define OFF_W1V (OFF_AGG + SZ_AGG)
#define SCRATCH_TOTAL (OFF_W1V + 2*DD)

__device__ float g_scratch[SCRATCH_TOTAL];

// fp16 pool
#define HW1 0
#define HW2 (HW1 + HH*DD)
#define HX0 (HW2 + HH*DD)
#define HX1 (HX0 + NN*BB*DD)
#define HC1 (HX1 + NN*BB*DD)
#define HC2 (HC1 + HH*DD)
#define HM  (HC2 + HH*DD)
#define HB  (HM  + HH*DD)
#define HXB (HB  + DD*DD)
#define HXC (HXB + NN*BB*DD)
#define HYC (HXC + NN*BB*HH)
#define HXM (HYC + NN*BB*HH)
#define HYM (HXM + NN*BB*HH)
#define HALF_TOTAL (HYM + NN*BB*HH)
__device__ __align__(16) __half g_half[HALF_TOTAL];

// tanh via MUFU.TANH
__device__ __forceinline__ float ftanh(float x) {
    float y;
    asm("tanh.approx.f32 %0, %1;" : "=f"(y) : "f"(x));
    return y;
}

__device__ __forceinline__ uint32_t smem_u32(const void* p) {
    uint32_t a;
    asm("{ .reg .u64 t; cvta.to.shared.u64 t, %1; cvt.u32.u64 %0, t; }" : "=r"(a) : "l"(p));
    return a;
}

#define LDSM4(r0, r1, r2, r3, addr) \
    asm volatile("ldmatrix.sync.aligned.m8n8.x4.shared.b16 {%0,%1,%2,%3}, [%4];" \
        : "=r"(r0), "=r"(r1), "=r"(r2), "=r"(r3) : "r"(addr))

#define MMA16816(d, a0, a1, a2, a3, b0, b1) \
    asm volatile("mma.sync.aligned.m16n8k16.row.col.f32.f16.f16.f32 " \
        "{%0,%1,%2,%3}, {%4,%5,%6,%7}, {%8,%9}, {%0,%1,%2,%3};" \
        : "+f"((d)[0]), "+f"((d)[1]), "+f"((d)[2]), "+f"((d)[3]) \
        : "r"(a0), "r"(a1), "r"(a2), "r"(a3), "r"(b0), "r"(b1))

#define CP_ASYNC16(sa, ga) \
    asm volatile("cp.async.cg.shared.global [%0], [%1], 16;" :: "r"(sa), "l"(ga))
#define CP_COMMIT() asm volatile("cp.async.commit_group;")
#define CP_WAIT0()  asm volatile("cp.async.wait_group 0;")

// 128B-row swizzle
__device__ __forceinline__ uint32_t sw128(uint32_t row, uint32_t chunk) {
    return row * 128u + ((chunk * 16u) ^ ((row & 7u) << 4));
}

// ---------------------------------------------------------------------------
// Coalesced weight transpose+convert (unchanged)
// ---------------------------------------------------------------------------
__global__ void wtrans(
    const float* __restrict__ Wd1, const float* __restrict__ Wd2,
    const float* __restrict__ Wc1, const float* __restrict__ Wc2,
    const float* __restrict__ Wm,  const float* __restrict__ Wb,
    __half* __restrict__ HP)
{
    const int z = blockIdx.z;
    const float* W; __half* wt; int N;
    switch (z) {
        case 0: W = Wd1; wt = HP + HW1; N = HH; break;
        case 1: W = Wd2; wt = HP + HW2; N = HH; break;
        case 2: W = Wc1; wt = HP + HC1; N = HH; break;
        case 3: W = Wc2; wt = HP + HC2; N = HH; break;
        case 4: W = Wm;  wt = HP + HM;  N = HH; break;
        default: W = Wb; wt = HP + HB;  N = DD; break;
    }
    const int h0 = blockIdx.x * 64;
    if (h0 >= N) return;
    const int d0 = blockIdx.y * 64;
    const int t = threadIdx.x;

    __shared__ __half tile[64][66];
#pragma unroll
    for (int i = 0; i < 16; i++) {
        int idx = i * 256 + t;
        int dr = idx >> 6, hc = idx & 63;
        tile[hc][dr] = __float2half_rn(W[(size_t)(d0 + dr) * N + h0 + hc]);
    }
    __syncthreads();
#pragma unroll
    for (int i = 0; i < 16; i++) {
        int idx = i * 256 + t;
        int hr = idx >> 6, dc = idx & 63;
        wt[(size_t)(h0 + hr) * DD + d0 + dc] = tile[hr][dc];
    }
}

// ---------------------------------------------------------------------------
// Remaining prep: x converts + w1v (unchanged)
// ---------------------------------------------------------------------------
__global__ void prep_rest(
    const float* __restrict__ x0, const float* __restrict__ x1,
    const float* __restrict__ Wp1, const float* __restrict__ vp,
    __half* __restrict__ HP, float* __restrict__ w1v)
{
    const int task = blockIdx.y;
    const int bx = blockIdx.x;
    const int tid = threadIdx.x;

    if (task < 2) {
        const float* x = (task == 0) ? x0 : x1;
        __half* xh = HP + ((task == 0) ? HX0 : HX1);
        int i = bx * 1024 + tid * 4;
        float4 v = *(const float4*)(x + i);
        __half2* o = (__half2*)(xh + i);
        o[0] = __floats2half2_rn(v.x, v.y);
        o[1] = __floats2half2_rn(v.z, v.w);
    } else {
        if (bx >= 256) return;
        int j = bx * 8 + (tid >> 5);
        int lane = tid & 31;
        const float* r = Wp1 + (size_t)j * HH;
        float acc = 0.0f;
#pragma unroll
        for (int h = lane; h < HH; h += 32) acc += r[h] * vp[h];
#pragma unroll
        for (int o = 16; o; o >>= 1) acc += __shfl_xor_sync(0xffffffffu, acc, o);
        if (lane == 0) w1v[j] = acc;
    }
}

// ---------------------------------------------------------------------------
// mma.sync fp16 dot-attention scores — R6 best-measured variant (unchanged).
// ---------------------------------------------------------------------------
#define MOFF_Y  0
#define MOFF_V  4096
#define MOFF_S  5120
#define MOFF_A  8192
#define MOFF_B  40960
#define MSMEM   106496

__global__ __launch_bounds__(512, 1) void dot_scores_mma(
    const float* __restrict__ x0, const float* __restrict__ x1,
    const __half* __restrict__ w1t, const __half* __restrict__ w2t,
    const float* __restrict__ vd1, const float* __restrict__ vd2,
    float* __restrict__ sp1, float* __restrict__ sp2)
{
    extern __shared__ char smc[];
    const uint32_t sb = smem_u32(smc);

    const int hc  = blockIdx.x;
    const int m   = blockIdx.y;
    const int att = blockIdx.z & 1;
    const int b   = blockIdx.z >> 1;

    const float* x = att ? x1 : x0;
    const float* y = att ? x0 : x1;
    const __half* wt = att ? w2t : w1t;
    const float* v = att ? vd2 : vd1;
    float* spart = att ? sp2 : sp1;

    const int t = threadIdx.x;
    const int lane = t & 31, wid = t >> 5;
    const int wn = wid & 3, whi = wid >> 2;
    const int lane15 = lane & 15, lhalf = lane >> 4;

    float* ysm = (float*)(smc + MOFF_Y);
    float* vsm = (float*)(smc + MOFF_V);
    float* ssm = (float*)(smc + MOFF_S);

    ((float2*)ysm)[t] = ((const float2*)(y + ((size_t)b * NN + m) * DD))[t];
    if (t < 64) ((float4*)vsm)[t] = ((const float4*)(v + hc * 256))[t];
    if (t < 128) ssm[t] = 0.0f;

    const float* xg = x + (size_t)b * NN * DD;
    const __half* wg = wt + (size_t)(hc * 256) * DD;

    const int an = t >> 2, ac = t & 3;
    const uint32_t a_st0 = sw128(an, ac);
    const uint32_t a_st1 = sw128(an, ac + 4);
    const int br = t >> 1, bc4 = (t & 1) * 4;
    uint32_t b_st[4];
#pragma unroll
    for (int j = 0; j < 4; j++) b_st[j] = sw128(br, bc4 + j);

    float xs[16];

#define ISSUE_B(kt, buf) do { \
        const __half* bp_ = wg + (size_t)br * DD + (kt) * 64 + bc4 * 8; \
        uint32_t Bb_ = sb + MOFF_B + (buf) * 32768u; \
        CP_ASYNC16(Bb_ + b_st[0], bp_); \
        CP_ASYNC16(Bb_ + b_st[1], bp_ + 8); \
        CP_ASYNC16(Bb_ + b_st[2], bp_ + 16); \
        CP_ASYNC16(Bb_ + b_st[3], bp_ + 24); \
        CP_COMMIT(); \
    } while (0)

#define LOAD_X(kt) do { \
        const float* xp_ = xg + (size_t)an * DD + (kt) * 64 + ac * 8; \
        *(float4*)&xs[0]  = *(const float4*)xp_; \
        *(float4*)&xs[4]  = *(const float4*)(xp_ + 4); \
        *(float4*)&xs[8]  = *(const float4*)(xp_ + 32); \
        *(float4*)&xs[12] = *(const float4*)(xp_ + 36); \
    } while (0)

#define STORE_A(kt, buf) do { \
        int kb_ = (kt) * 64 + ac * 8; \
        union { __half h[8]; uint4 q; } u0_, u1_; \
        _Pragma("unroll") \
        for (int j_ = 0; j_ < 8; j_++) { \
            u0_.h[j_] = __float2half_rn(xs[j_]     * ysm[kb_ + j_]); \
            u1_.h[j_] = __float2half_rn(xs[j_ + 8] * ysm[kb_ + 32 + j_]); \
        } \
        char* Ab_ = smc + MOFF_A + (buf) * 16384; \
        *(uint4*)(Ab_ + a_st0) = u0_.q; \
        *(uint4*)(Ab_ + a_st1) = u1_.q; \
    } while (0)

    float acc[2][8][4];
#pragma unroll
    for (int i = 0; i < 2; i++)
#pragma unroll
        for (int j = 0; j < 8; j++)
#pragma unroll
            for (int k = 0; k < 4; k++) acc[i][j][k] = 0.0f;

    ISSUE_B(0, 0);
    LOAD_X(0);
    __syncthreads();
    STORE_A(0, 0);
    CP_WAIT0();
    __syncthreads();

    uint32_t a_row[2], b_row[4];
#pragma unroll
    for (int mi = 0; mi < 2; mi++) a_row[mi] = wn * 32 + mi * 16 + lane15;
#pragma unroll
    for (int nj = 0; nj < 4; nj++) b_row[nj] = whi * 64 + nj * 16 + lane15;

    for (int kt = 0; kt < 16; kt++) {
        const int buf = kt & 1;
        if (kt < 15) { ISSUE_B(kt + 1, buf ^ 1); LOAD_X(kt + 1); }

        const uint32_t Ah = sb + MOFF_A + buf * 16384u;
        const uint32_t Bh = sb + MOFF_B + buf * 32768u;

#pragma unroll
        for (int ks = 0; ks < 4; ks++) {
            const uint32_t cidx = ks * 2 + lhalf;
            uint32_t a[2][4], bb[4][4];
#pragma unroll
            for (int mi = 0; mi < 2; mi++)
                LDSM4(a[mi][0], a[mi][1], a[mi][2], a[mi][3], Ah + sw128(a_row[mi], cidx));
#pragma unroll
            for (int nj = 0; nj < 4; nj++)
                LDSM4(bb[nj][0], bb[nj][1], bb[nj][2], bb[nj][3], Bh + sw128(b_row[nj], cidx));
#pragma unroll
            for (int mi = 0; mi < 2; mi++)
#pragma unroll
                for (int nj = 0; nj < 4; nj++) {
                    MMA16816(acc[mi][nj*2+0], a[mi][0], a[mi][1], a[mi][2], a[mi][3], bb[nj][0], bb[nj][2]);
                    MMA16816(acc[mi][nj*2+1], a[mi][0], a[mi][1], a[mi][2], a[mi][3], bb[nj][1], bb[nj][3]);
                }
        }

        if (kt < 15) { STORE_A(kt + 1, buf ^ 1); CP_WAIT0(); }
        __syncthreads();
    }

    float rs[2][2] = {{0.0f, 0.0f}, {0.0f, 0.0f}};
#pragma unroll
    for (int mi = 0; mi < 2; mi++)
#pragma unroll
        for (int hj = 0; hj < 8; hj++) {
            int hcol = whi * 64 + hj * 8 + (lane & 3) * 2;
            float v0 = vsm[hcol], v1 = vsm[hcol + 1];
            rs[mi][0] += ftanh(acc[mi][hj][0]) * v0 + ftanh(acc[mi][hj][1]) * v1;
            rs[mi][1] += ftanh(acc[mi][hj][2]) * v0 + ftanh(acc[mi][hj][3]) * v1;
        }
#pragma unroll
    for (int o = 1; o <= 2; o <<= 1) {
        rs[0][0] += __shfl_xor_sync(0xffffffffu, rs[0][0], o);
        rs[0][1] += __shfl_xor_sync(0xffffffffu, rs[0][1], o);
        rs[1][0] += __shfl_xor_sync(0xffffffffu, rs[1][0], o);
        rs[1][1] += __shfl_xor_sync(0xffffffffu, rs[1][1], o);
    }
    if ((lane & 3) == 0) {
        int r = wn * 32 + (lane >> 2);
        atomicAdd(&ssm[r],      rs[0][0]);
        atomicAdd(&ssm[r + 8],  rs[0][1]);
        atomicAdd(&ssm[r + 16], rs[1][0]);
        atomicAdd(&ssm[r + 24], rs[1][1]);
    }
    __syncthreads();
    if (t < 128)
        spart[(((size_t)b * NN + m) * 2 + hc) * NN + t] = ssm[t];
#undef ISSUE_B
#undef LOAD_X
#undef STORE_A
}

// ---------------------------------------------------------------------------
// fp16 mma projections — now 2 CTAs/SM (regs 2x117x256=60K<64K, smem 128K<228K)
// ---------------------------------------------------------------------------
#define POFF_A 0
#define POFF_B 32768
#define PSMEM  65536

__global__ __launch_bounds__(256, 2) void proj_mma(
    const __half* __restrict__ xh0, const __half* __restrict__ xh1,
    __half* __restrict__ HP)
{
    const __half* A; const __half* W; __half* Ch; int N;
    switch (blockIdx.z) {
        case 0: A = xh0; W = HP + HC1; Ch = HP + HXC; N = HH; break;
        case 1: A = xh1; W = HP + HC2; Ch = HP + HYC; N = HH; break;
        case 2: A = xh0; W = HP + HM;  Ch = HP + HXM; N = HH; break;
        case 3: A = xh1; W = HP + HM;  Ch = HP + HYM; N = HH; break;
        default: A = xh0; W = HP + HB; Ch = HP + HXB; N = DD; break;
    }
    const int bn = blockIdx.x * 128;
    if (bn >= N) return;
    const int bm = blockIdx.y * 128;

    extern __shared__ char smc[];
    const uint32_t sb = smem_u32(smc);
    const int t = threadIdx.x, lane = t & 31, wid = t >> 5;
    const int wm = wid & 3, whn = wid >> 2;
    const int lane15 = lane & 15, lhalf = lane >> 4;

    const int r = t >> 1, cc4 = (t & 1) * 4;
    uint32_t st_off[4];
#pragma unroll
    for (int j = 0; j < 4; j++) st_off[j] = sw128(r, cc4 + j);
    const __half* ag = A + (size_t)(bm + r) * DD + cc4 * 8;
    const __half* wgp = W + (size_t)(bn + r) * DD + cc4 * 8;

#define P_ISSUE(kt, buf) do { \
        uint32_t Ab_ = sb + POFF_A + (buf) * 16384u; \
        uint32_t Bb_ = sb + POFF_B + (buf) * 16384u; \
        const __half* ap_ = ag + (kt) * 64; \
        const __half* bp_ = wgp + (kt) * 64; \
        _Pragma("unroll") \
        for (int j_ = 0; j_ < 4; j_++) { \
            CP_ASYNC16(Ab_ + st_off[j_], ap_ + j_ * 8); \
            CP_ASYNC16(Bb_ + st_off[j_], bp_ + j_ * 8); \
        } \
        CP_COMMIT(); \
    } while (0)

    float acc[2][8][4];
#pragma unroll
    for (int i = 0; i < 2; i++)
#pragma unroll
        for (int j = 0; j < 8; j++)
#pragma unroll
            for (int k = 0; k < 4; k++) acc[i][j][k] = 0.0f;

    P_ISSUE(0, 0);
    CP_WAIT0();
    __syncthreads();

    uint32_t a_row[2], b_row[4];
#pragma unroll
    for (int mi = 0; mi < 2; mi++) a_row[mi] = wm * 32 + mi * 16 + lane15;
#pragma unroll
    for (int nj = 0; nj < 4; nj++) b_row[nj] = whn * 64 + nj * 16 + lane15;

    for (int kt = 0; kt < 16; kt++) {
        const int buf = kt & 1;
        if (kt < 15) P_ISSUE(kt + 1, buf ^ 1);

        const uint32_t Ah = sb + POFF_A + buf * 16384u;
        const uint32_t Bh = sb + POFF_B + buf * 16384u;

#pragma unroll
        for (int ks = 0; ks < 4; ks++) {
            const uint32_t cidx = ks * 2 + lhalf;
            uint32_t a[2][4], bb[4][4];
#pragma unroll
            for (int mi = 0; mi < 2; mi++)
                LDSM4(a[mi][0], a[mi][1], a[mi][2], a[mi][3], Ah + sw128(a_row[mi], cidx));
#pragma unroll
            for (int nj = 0; nj < 4; nj++)
                LDSM4(bb[nj][0], bb[nj][1], bb[nj][2], bb[nj][3], Bh + sw128(b_row[nj], cidx));
#pragma unroll
            for (int mi = 0; mi < 2; mi++)
#pragma unroll
                for (int nj = 0; nj < 4; nj++) {
                    MMA16816(acc[mi][nj*2+0], a[mi][0], a[mi][1], a[mi][2], a[mi][3], bb[nj][0], bb[nj][2]);
                    MMA16816(acc[mi][nj*2+1], a[mi][0], a[mi][1], a[mi][2], a[mi][3], bb[nj][1], bb[nj][3]);
                }
        }

        CP_WAIT0();
        __syncthreads();
    }

#pragma unroll
    for (int mi = 0; mi < 2; mi++) {
        int row = bm + wm * 32 + mi * 16 + (lane >> 2);
#pragma unroll
        for (int nj8 = 0; nj8 < 8; nj8++) {
            int col = bn + whn * 64 + nj8 * 8 + (lane & 3) * 2;
            *(__half2*)&Ch[(size_t)row * N + col] =
                __floats2half2_rn(acc[mi][nj8][0], acc[mi][nj8][1]);
            *(__half2*)&Ch[(size_t)(row + 8) * N + col] =
                __floats2half2_rn(acc[mi][nj8][2], acc[mi][nj8][3]);
        }
    }
#undef P_ISSUE
}

// ---------------------------------------------------------------------------
// Bilinear scores on tensor cores — now 2 CTAs/SM.
// ---------------------------------------------------------------------------
#define BOFF_A 0
#define BOFF_B 32768
#define BSMEM  49152

__global__ __launch_bounds__(256, 2) void bilin_tc(
    const __half* __restrict__ xh1, const __half* __restrict__ xbh,
    float* __restrict__ sbuf)
{
    const int half_n = blockIdx.x;
    const int b = blockIdx.y;
    const __half* A = xh1 + (size_t)b * NN * DD;
    const __half* Bq = xbh + (size_t)b * NN * DD + (size_t)half_n * 64 * DD;

    extern __shared__ char smc[];
    const uint32_t sb = smem_u32(smc);
    const int t = threadIdx.x, lane = t & 31, wid = t >> 5;
    const int wm = wid & 3, whn = wid >> 2;
    const int lane15 = lane & 15, lhalf = lane >> 4;

    const int ra = t >> 1, ca4 = (t & 1) * 4;
    uint32_t a_off[4];
#pragma unroll
    for (int j = 0; j < 4; j++) a_off[j] = sw128(ra, ca4 + j);
    const __half* ag = A + (size_t)ra * DD + ca4 * 8;
    const int rb = t >> 2, cb2 = (t & 3) * 2;
    const uint32_t b_off0 = sw128(rb, cb2), b_off1 = sw128(rb, cb2 + 1);
    const __half* bg = Bq + (size_t)rb * DD + cb2 * 8;

#define BL_ISSUE(kt, buf) do { \
        uint32_t Ab_ = sb + BOFF_A + (buf) * 16384u; \
        uint32_t Bb_ = sb + BOFF_B + (buf) * 8192u; \
        const __half* ap_ = ag + (kt) * 64; \
        const __half* bp_ = bg + (kt) * 64; \
        _Pragma("unroll") \
        for (int j_ = 0; j_ < 4; j_++) CP_ASYNC16(Ab_ + a_off[j_], ap_ + j_ * 8); \
        CP_ASYNC16(Bb_ + b_off0, bp_); \
        CP_ASYNC16(Bb_ + b_off1, bp_ + 8); \
        CP_COMMIT(); \
    } while (0)

    float acc[2][4][4];
#pragma unroll
    for (int i = 0; i < 2; i++)
#pragma unroll
        for (int j = 0; j < 4; j++)
#pragma unroll
            for (int k = 0; k < 4; k++) acc[i][j][k] = 0.0f;

    BL_ISSUE(0, 0);
    CP_WAIT0();
    __syncthreads();

    uint32_t a_row[2], b_row[2];
#pragma unroll
    for (int mi = 0; mi < 2; mi++) a_row[mi] = wm * 32 + mi * 16 + lane15;
#pragma unroll
    for (int nj = 0; nj < 2; nj++) b_row[nj] = whn * 32 + nj * 16 + lane15;

    for (int kt = 0; kt < 16; kt++) {
        const int buf = kt & 1;
        if (kt < 15) BL_ISSUE(kt + 1, buf ^ 1);

        const uint32_t Ah = sb + BOFF_A + buf * 16384u;
        const uint32_t Bh = sb + BOFF_B + buf * 8192u;

#pragma unroll
        for (int ks = 0; ks < 4; ks++) {
            const uint32_t cidx = ks * 2 + lhalf;
            uint32_t a[2][4], bb[2][4];
#pragma unroll
            for (int mi = 0; mi < 2; mi++)
                LDSM4(a[mi][0], a[mi][1], a[mi][2], a[mi][3], Ah + sw128(a_row[mi], cidx));
#pragma unroll
            for (int nj = 0; nj < 2; nj++)
                LDSM4(bb[nj][0], bb[nj][1], bb[nj][2], bb[nj][3], Bh + sw128(b_row[nj], cidx));
#pragma unroll
            for (int mi = 0; mi < 2; mi++)
#pragma unroll
                for (int nj = 0; nj < 2; nj++) {
                    MMA16816(acc[mi][nj*2+0], a[mi][0], a[mi][1], a[mi][2], a[mi][3], bb[nj][0], bb[nj][2]);
                    MMA16816(acc[mi][nj*2+1], a[mi][0], a[mi][1], a[mi][2], a[mi][3], bb[nj][1], bb[nj][3]);
                }
        }

        CP_WAIT0();
        __syncthreads();
    }

#pragma unroll
    for (int mi = 0; mi < 2; mi++) {
        int row = wm * 32 + mi * 16 + (lane >> 2);
#pragma unroll
        for (int nj8 = 0; nj8 < 4; nj8++) {
            int col = half_n * 64 + whn * 32 + nj8 * 8 + (lane & 3) * 2;
            sbuf[((size_t)b * NN + row) * NN + col]         = acc[mi][nj8][0];
            sbuf[((size_t)b * NN + row) * NN + col + 1]     = acc[mi][nj8][1];
            sbuf[((size_t)b * NN + row + 8) * NN + col]     = acc[mi][nj8][2];
            sbuf[((size_t)b * NN + row + 8) * NN + col + 1] = acc[mi][nj8][3];
        }
    }
#undef BL_ISSUE
}

// ---------------------------------------------------------------------------
// Concat + minus scores, 4-m blocked, fp16 inputs (unchanged)
// ---------------------------------------------------------------------------
__global__ __launch_bounds__(256) void pair_scores4(
    const __half* __restrict__ HP,
    const float* __restrict__ vcv, const float* __restrict__ vmv,
    float* __restrict__ sc, float* __restrict__ smn)
{
    const int m0 = blockIdx.x * 4, b = blockIdx.y, z = blockIdx.z;
    const __half* p = HP + (z ? HXM : HXC);
    const __half* q = HP + (z ? HYM : HYC);
    const float* v = z ? vmv : vcv;
    float* s = z ? smn : sc;
    const float sign = z ? -1.0f : 1.0f;

    const int t = threadIdx.x, lane = t & 31, w = t >> 5;
    __shared__ float qs[4][HH], vs[HH];
    {
        uint4 qv = ((const uint4*)(q + ((size_t)b * NN + m0) * HH))[t];
        const __half2* h2 = (const __half2*)&qv;
        float* dst = &qs[0][0] + t * 8;
        float2 f0 = __half22float2(h2[0]), f1 = __half22float2(h2[1]);
        float2 f2 = __half22float2(h2[2]), f3 = __half22float2(h2[3]);
        dst[0] = f0.x; dst[1] = f0.y; dst[2] = f1.x; dst[3] = f1.y;
        dst[4] = f2.x; dst[5] = f2.y; dst[6] = f3.x; dst[7] = f3.y;
        if (t < 128) ((float4*)vs)[t] = ((const float4*)v)[t];
    }
    __syncthreads();

    const __half* pb = p + (size_t)b * NN * HH;
    for (int n = w; n < NN; n += 8) {
        const __half* pr = pb + (size_t)n * HH;
        float a0 = 0.0f, a1 = 0.0f, a2 = 0.0f, a3 = 0.0f;
#pragma unroll
        for (int h = 0; h < HH; h += 32) {
            int hh = h + lane;
            float pv = __half2float(pr[hh]), vv = vs[hh];
            a0 += vv * ftanh(fmaf(sign, qs[0][hh], pv));
            a1 += vv * ftanh(fmaf(sign, qs[1][hh], pv));
            a2 += vv * ftanh(fmaf(sign, qs[2][hh], pv));
            a3 += vv * ftanh(fmaf(sign, qs[3][hh], pv));
        }
#pragma unroll
        for (int o = 16; o; o >>= 1) {
            a0 += __shfl_xor_sync(0xffffffffu, a0, o);
            a1 += __shfl_xor_sync(0xffffffffu, a1, o);
            a2 += __shfl_xor_sync(0xffffffffu, a2, o);
            a3 += __shfl_xor_sync(0xffffffffu, a3, o);
        }
        if (lane == 0) {
            s[((size_t)b * NN + m0 + 0) * NN + n] = a0;
            s[((size_t)b * NN + m0 + 1) * NN + n] = a1;
            s[((size_t)b * NN + m0 + 2) * NN + n] = a2;
            s[((size_t)b * NN + m0 + 3) * NN + n] = a3;
        }
    }
}

// ---------------------------------------------------------------------------
// Fused: softmaxes + weighted sums + max + agg_rep, 8 m's per CTA (x reuse x8).
// grid (16, 8), 256 threads. smem 40x128 floats = 20KB.
// ---------------------------------------------------------------------------
__global__ __launch_bounds__(256) void fuse_att8(
    const float* __restrict__ sc,  const float* __restrict__ sb,
    const float* __restrict__ smn, const float* __restrict__ sd1,
    const float* __restrict__ sd2,
    const float* __restrict__ x0,  const float* __restrict__ x1,
    float* __restrict__ aggrep)
{
    const int m0 = blockIdx.x * 8, b = blockIdx.y;
    const int t = threadIdx.x, lane = t & 31, w = t >> 5;
    __shared__ float aw[40][NN];   // row = att*8 + mi

    if (t < 128) {
        const int n = t;
#pragma unroll
        for (int mi = 0; mi < 8; mi++) {
            const size_t bm = (size_t)b * NN + m0 + mi;
            aw[0 * 8 + mi][n] = sc [bm * NN + n];
            aw[1 * 8 + mi][n] = sb [bm * NN + n];
            aw[2 * 8 + mi][n] = smn[bm * NN + n];
            aw[3 * 8 + mi][n] = sd1[(bm * 2 + 0) * NN + n] + sd1[(bm * 2 + 1) * NN + n];
            aw[4 * 8 + mi][n] = sd2[(bm * 2 + 0) * NN + n] + sd2[(bm * 2 + 1) * NN + n];
        }
    }
    __syncthreads();

    for (int row = w; row < 40; row += 8) {
        float v0 = aw[row][lane], v1 = aw[row][lane + 32];
        float v2 = aw[row][lane + 64], v3 = aw[row][lane + 96];
        float mx = fmaxf(fmaxf(v0, v1), fmaxf(v2, v3));
#pragma unroll
        for (int o = 16; o; o >>= 1) mx = fmaxf(mx, __shfl_xor_sync(0xffffffffu, mx, o));
        float e0 = __expf(v0 - mx), e1 = __expf(v1 - mx);
        float e2 = __expf(v2 - mx), e3 = __expf(v3 - mx);
        float sm = e0 + e1 + e2 + e3;
#pragma unroll
        for (int o = 16; o; o >>= 1) sm += __shfl_xor_sync(0xffffffffu, sm, o);
        float inv = 1.0f / sm;
        aw[row][lane]      = e0 * inv; aw[row][lane + 32] = e1 * inv;
        aw[row][lane + 64] = e2 * inv; aw[row][lane + 96] = e3 * inv;
    }
    __syncthreads();

    const int d = t * 4;
    float4 acc[5][8];
#pragma unroll
    for (int a = 0; a < 5; a++)
#pragma unroll
        for (int mi = 0; mi < 8; mi++) acc[a][mi] = make_float4(0.f, 0.f, 0.f, 0.f);

    const float* x0b = x0 + (size_t)b * NN * DD;
    const float* x1b = x1 + (size_t)b * NN * DD;
    for (int n = 0; n < NN; n++) {
        float4 xv = *(const float4*)(x0b + (size_t)n * DD + d);
        float4 yv = *(const float4*)(x1b + (size_t)n * DD + d);
#pragma unroll
        for (int mi = 0; mi < 8; mi++) {
            float w0 = aw[0 * 8 + mi][n], w1 = aw[1 * 8 + mi][n];
            float w2 = aw[2 * 8 + mi][n], w3 = aw[3 * 8 + mi][n];
            float w4 = aw[4 * 8 + mi][n];
            acc[0][mi].x = fmaf(w0, xv.x, acc[0][mi].x); acc[0][mi].y = fmaf(w0, xv.y, acc[0][mi].y);
            acc[0][mi].z = fmaf(w0, xv.z, acc[0][mi].z); acc[0][mi].w = fmaf(w0, xv.w, acc[0][mi].w);
            acc[1][mi].x = fmaf(w1, xv.x, acc[1][mi].x); acc[1][mi].y = fmaf(w1, xv.y, acc[1][mi].y);
            acc[1][mi].z = fmaf(w1, xv.z, acc[1][mi].z); acc[1][mi].w = fmaf(w1, xv.w, acc[1][mi].w);
            acc[2][mi].x = fmaf(w2, xv.x, acc[2][mi].x); acc[2][mi].y = fmaf(w2, xv.y, acc[2][mi].y);
            acc[2][mi].z = fmaf(w2, xv.z, acc[2][mi].z); acc[2][mi].w = fmaf(w2, xv.w, acc[2][mi].w);
            acc[3][mi].x = fmaf(w3, xv.x, acc[3][mi].x); acc[3][mi].y = fmaf(w3, xv.y, acc[3][mi].y);
            acc[3][mi].z = fmaf(w3, xv.z, acc[3][mi].z); acc[3][mi].w = fmaf(w3, xv.w, acc[3][mi].w);
            acc[4][mi].x = fmaf(w4, yv.x, acc[4][mi].x); acc[4][mi].y = fmaf(w4, yv.y, acc[4][mi].y);
            acc[4][mi].z = fmaf(w4, yv.z, acc[4][mi].z); acc[4][mi].w = fmaf(w4, yv.w, acc[4][mi].w);
        }
    }

#pragma unroll
    for (int mi = 0; mi < 8; mi++) {
        const size_t bm = (size_t)b * NN + m0 + mi;
        float4 xm1 = *(const float4*)(x1b + (size_t)(m0 + mi) * DD + d);
        float4 ag;
        ag.x = fmaxf(xm1.x, fmaxf(fmaxf(acc[3][mi].x, acc[0][mi].x),
                                  fmaxf(fmaxf(acc[4][mi].x, acc[1][mi].x), acc[2][mi].x)));
        ag.y = fmaxf(xm1.y, fmaxf(fmaxf(acc[3][mi].y, acc[0][mi].y),
                                  fmaxf(fmaxf(acc[4][mi].y, acc[1][mi].y), acc[2][mi].y)));
        ag.z = fmaxf(xm1.z, fmaxf(fmaxf(acc[3][mi].z, acc[0][mi].z),
                                  fmaxf(fmaxf(acc[4][mi].z, acc[1][mi].z), acc[2][mi].z)));
        ag.w = fmaxf(xm1.w, fmaxf(fmaxf(acc[3][mi].w, acc[0][mi].w),
                                  fmaxf(fmaxf(acc[4][mi].w, acc[1][mi].w), acc[2][mi].w)));
        float* arow = aggrep + bm * (2 * DD);
        *(float4*)(arow + d)      = xm1;
        *(float4*)(arow + DD + d) = ag;
    }
}

// ---------------------------------------------------------------------------
// Final head (unchanged)
// ---------------------------------------------------------------------------
__global__ __launch_bounds__(256) void final_kernel(
    const float* __restrict__ aggrep, const float* __restrict__ w1v,
    const float* __restrict__ Wpred,  const float* __restrict__ bpred,
    float* __restrict__ out)
{
    const int b = blockIdx.x;
    const int t = threadIdx.x, lane = t & 31, w = t >> 5;
    __shared__ float sp[NN];
    __shared__ float r0[8], r1[8];
    const float* ab = aggrep + (size_t)b * NN * (2 * DD);

    for (int mm = w; mm < NN; mm += 8) {
        const float* ar = ab + (size_t)mm * (2 * DD);
        float acc = 0.0f;
#pragma unroll
        for (int j = lane; j < 2 * DD; j += 32) acc += ar[j] * w1v[j];
#pragma unroll
        for (int o = 16; o; o >>= 1) acc += __shfl_xor_sync(0xffffffffu, acc, o);
        if (lane == 0) sp[mm] = acc;
    }
    __syncthreads();
    if (w == 0) {
        float v0 = sp[lane], v1 = sp[lane + 32], v2 = sp[lane + 64], v3 = sp[lane + 96];
        float mx = fmaxf(fmaxf(v0, v1), fmaxf(v2, v3));
#pragma unroll
        for (int o = 16; o; o >>= 1) mx = fmaxf(mx, __shfl_xor_sync(0xffffffffu, mx, o));
        float e0 = __expf(v0 - mx), e1 = __expf(v1 - mx);
        float e2 = __expf(v2 - mx), e3 = __expf(v3 - mx);
        float sm = e0 + e1 + e2 + e3;
#pragma unroll
        for (int o = 16; o; o >>= 1) sm += __shfl_xor_sync(0xffffffffu, sm, o);
        float inv = 1.0f / sm;
        sp[lane] = e0 * inv; sp[lane + 32] = e1 * inv;
        sp[lane + 64] = e2 * inv; sp[lane + 96] = e3 * inv;
    }
    __syncthreads();

    float rp[8];
#pragma unroll
    for (int k = 0; k < 8; k++) rp[k] = 0.0f;
    for (int mm = 0; mm < NN; mm++) {
        float wgt = sp[mm];
        const float* ar = ab + (size_t)mm * (2 * DD);
#pragma unroll
        for (int k = 0; k < 8; k++) rp[k] = fmaf(wgt, ar[t + k * 256], rp[k]);
    }
    float p0 = 0.0f, p1 = 0.0f;
#pragma unroll
    for (int k = 0; k < 8; k++) {
        int j = t + k * 256;
        p0 = fmaf(rp[k], Wpred[(size_t)j * 2 + 0], p0);
        p1 = fmaf(rp[k], Wpred[(size_t)j * 2 + 1], p1);
    }
#pragma unroll
    for (int o = 16; o; o >>= 1) {
        p0 += __shfl_xor_sync(0xffffffffu, p0, o);
        p1 += __shfl_xor_sync(0xffffffffu, p1, o);
    }
    if (lane == 0) { r0[w] = p0; r1[w] = p1; }
    __syncthreads();
    if (t == 0) {
        float s0 = 0.0f, s1 = 0.0f;
#pragma unroll
        for (int i = 0; i < 8; i++) { s0 += r0[i]; s1 += r1[i]; }
        out[b * 2 + 0] = fmaxf(s0 + bpred[0], 0.0f);
        out[b * 2 + 1] = fmaxf(s1 + bpred[1], 0.0f);
    }
}

// ---------------------------------------------------------------------------
extern "C" void kernel_launch(void* const* d_in, const int* in_sizes, int n_in,
                              void* d_out, int out_size)
{
    (void)in_sizes; (void)n_in; (void)out_size;
    float* S = nullptr;
    cudaGetSymbolAddress((void**)&S, g_scratch);
    __half* HP = nullptr;
    cudaGetSymbolAddress((void**)&HP, g_half);

    const float* x0    = (const float*)d_in[0];
    const float* x1    = (const float*)d_in[1];
    const float* Wc1   = (const float*)d_in[2];
    const float* Wc2   = (const float*)d_in[3];
    const float* vc    = (const float*)d_in[4];
    const float* Wb    = (const float*)d_in[5];
    const float* Wd1   = (const float*)d_in[6];
    const float* vd1   = (const float*)d_in[7];
    const float* Wd2   = (const float*)d_in[8];
    const float* vd2   = (const float*)d_in[9];
    const float* Wm    = (const float*)d_in[10];
    const float* vm    = (const float*)d_in[11];
    const float* Wp1   = (const float*)d_in[14];
    const float* vp    = (const float*)d_in[16];
    const float* Wpred = (const float*)d_in[17];
    const float* bpred = (const float*)d_in[18];
    float* out = (float*)d_out;

    static cudaStream_t s_dot = nullptr;
    static cudaEvent_t ev_prep = nullptr, ev_dot = nullptr;
    static bool attrs_set = false;
    if (!attrs_set) {
        cudaFuncSetAttribute(dot_scores_mma,
                             cudaFuncAttributeMaxDynamicSharedMemorySize, MSMEM);
        cudaFuncSetAttribute(proj_mma,
                             cudaFuncAttributeMaxDynamicSharedMemorySize, PSMEM);
        cudaFuncSetAttribute(bilin_tc,
                             cudaFuncAttributeMaxDynamicSharedMemorySize, BSMEM);
        cudaStreamCreateWithFlags(&s_dot, cudaStreamNonBlocking);
        cudaEventCreateWithFlags(&ev_prep, cudaEventDisableTiming);
        cudaEventCreateWithFlags(&ev_dot, cudaEventDisableTiming);
        attrs_set = true;
    }

    __half* w1t = HP + HW1;
    __half* w2t = HP + HW2;
    __half* xh0 = HP + HX0;
    __half* xh1 = HP + HX1;
    __half* xbh = HP + HXB;

    // Prep (main stream)
    wtrans<<<dim3(16, 16, 6), 256>>>(Wd1, Wd2, Wc1, Wc2, Wm, Wb, HP);
    prep_rest<<<dim3(1024, 3), 256>>>(x0, x1, Wp1, vp, HP, S + OFF_W1V);
    cudaEventRecord(ev_prep, 0);

    // Fork: dominant dot kernel
    cudaStreamWaitEvent(s_dot, ev_prep, 0);
    dot_scores_mma<<<dim3(2, NN, 2 * BB), 512, MSMEM, s_dot>>>(
        x0, x1, w1t, w2t, vd1, vd2, S + OFF_SD1, S + OFF_SD2);
    cudaEventRecord(ev_dot, s_dot);

    // Main: projections, bilin on TC, pair scores
    proj_mma<<<dim3(8, 8, 5), 256, PSMEM>>>(xh0, xh1, HP);
    bilin_tc<<<dim3(2, BB), 256, BSMEM>>>(xh1, xbh, S + OFF_SB);
    pair_scores4<<<dim3(NN / 4, BB, 2), 256>>>(HP, vc, vm, S + OFF_SC, S + OFF_SMN);

    // Join + fused aggregation (8 m's per CTA) + final head
    cudaStreamWaitEvent(0, ev_dot, 0);
    fuse_att8<<<dim3(NN / 8, BB), 256>>>(S + OFF_SC, S + OFF_SB, S + OFF_SMN,
                                         S + OFF_SD1, S + OFF_SD2, x0, x1, S + OFF_AGG);
    final_kernel<<<BB, 256>>>(S + OFF_AGG, S + OFF_W1V, Wpred, bpred, out);
}

// round 16
// speedup vs baseline: 1.0050x; 1.0050x over previous
#include <cuda_runtime.h>
#include <cuda_fp16.h>
#include <cstdint>
#include <cstddef>

// ---------------------------------------------------------------------------
// Problem constants: B=8, N=M=128, H=512, D=2H=1024
// ---------------------------------------------------------------------------
#define BB   8
#define NN   128
#define HH   512
#define DD   1024

// Float scratch (scores + agg + w1v)
#define SZ_S    (BB*NN*NN)
#define SZ_SD   (BB*NN*2*NN)
#define SZ_AGG  (BB*NN*2*DD)
#define OFF_SC  0
#define OFF_SB  (OFF_SC + SZ_S)
#define OFF_SMN (OFF_SB + SZ_S)
#define OFF_SD1 (OFF_SMN + SZ_S)
#define OFF_SD2 (OFF_SD1 + SZ_SD)
#define OFF_AGG (OFF_SD2 + SZ_SD)
#define OFF_W1V (OFF_AGG + SZ_AGG)
#define SCRATCH_TOTAL (OFF_W1V + 2*DD)

__device__ float g_scratch[SCRATCH_TOTAL];

// fp16 pool
#define HW1 0
#define HW2 (HW1 + HH*DD)
#define HX0 (HW2 + HH*DD)
#define HX1 (HX0 + NN*BB*DD)
#define HC1 (HX1 + NN*BB*DD)
#define HC2 (HC1 + HH*DD)
#define HM  (HC2 + HH*DD)
#define HB  (HM  + HH*DD)
#define HXB (HB  + DD*DD)
#define HXC (HXB + NN*BB*DD)
#define HYC (HXC + NN*BB*HH)
#define HXM (HYC + NN*BB*HH)
#define HYM (HXM + NN*BB*HH)
#define HALF_TOTAL (HYM + NN*BB*HH)
__device__ __align__(16) __half g_half[HALF_TOTAL];

// tanh via MUFU.TANH
__device__ __forceinline__ float ftanh(float x) {
    float y;
    asm("tanh.approx.f32 %0, %1;" : "=f"(y) : "f"(x));
    return y;
}

__device__ __forceinline__ uint32_t smem_u32(const void* p) {
    uint32_t a;
    asm("{ .reg .u64 t; cvta.to.shared.u64 t, %1; cvt.u32.u64 %0, t; }" : "=r"(a) : "l"(p));
    return a;
}

#define LDSM4(r0, r1, r2, r3, addr) \
    asm volatile("ldmatrix.sync.aligned.m8n8.x4.shared.b16 {%0,%1,%2,%3}, [%4];" \
        : "=r"(r0), "=r"(r1), "=r"(r2), "=r"(r3) : "r"(addr))

#define MMA16816(d, a0, a1, a2, a3, b0, b1) \
    asm volatile("mma.sync.aligned.m16n8k16.row.col.f32.f16.f16.f32 " \
        "{%0,%1,%2,%3}, {%4,%5,%6,%7}, {%8,%9}, {%0,%1,%2,%3};" \
        : "+f"((d)[0]), "+f"((d)[1]), "+f"((d)[2]), "+f"((d)[3]) \
        : "r"(a0), "r"(a1), "r"(a2), "r"(a3), "r"(b0), "r"(b1))

#define CP_ASYNC16(sa, ga) \
    asm volatile("cp.async.cg.shared.global [%0], [%1], 16;" :: "r"(sa), "l"(ga))
#define CP_COMMIT() asm volatile("cp.async.commit_group;")
#define CP_WAIT0()  asm volatile("cp.async.wait_group 0;")

// 128B-row swizzle
__device__ __forceinline__ uint32_t sw128(uint32_t row, uint32_t chunk) {
    return row * 128u + ((chunk * 16u) ^ ((row & 7u) << 4));
}

// ---------------------------------------------------------------------------
// Weight transpose+convert for the DOT weights only (critical path).
// grid (8, 16, 2): z in {Wd1, Wd2}.
// ---------------------------------------------------------------------------
__global__ void wtrans_d(
    const float* __restrict__ Wd1, const float* __restrict__ Wd2,
    __half* __restrict__ HP)
{
    const float* W = blockIdx.z ? Wd2 : Wd1;
    __half* wt = HP + (blockIdx.z ? HW2 : HW1);
    const int h0 = blockIdx.x * 64;
    const int d0 = blockIdx.y * 64;
    const int t = threadIdx.x;

    __shared__ __half tile[64][66];
#pragma unroll
    for (int i = 0; i < 16; i++) {
        int idx = i * 256 + t;
        int dr = idx >> 6, hc = idx & 63;
        tile[hc][dr] = __float2half_rn(W[(size_t)(d0 + dr) * HH + h0 + hc]);
    }
    __syncthreads();
#pragma unroll
    for (int i = 0; i < 16; i++) {
        int idx = i * 256 + t;
        int hr = idx >> 6, dc = idx & 63;
        wt[(size_t)(h0 + hr) * DD + d0 + dc] = tile[hr][dc];
    }
}

// ---------------------------------------------------------------------------
// Remaining weight transposes (proj weights). grid (16, 16, 4).
// ---------------------------------------------------------------------------
__global__ void wtrans_rest(
    const float* __restrict__ Wc1, const float* __restrict__ Wc2,
    const float* __restrict__ Wm,  const float* __restrict__ Wb,
    __half* __restrict__ HP)
{
    const int z = blockIdx.z;
    const float* W; __half* wt; int N;
    switch (z) {
        case 0: W = Wc1; wt = HP + HC1; N = HH; break;
        case 1: W = Wc2; wt = HP + HC2; N = HH; break;
        case 2: W = Wm;  wt = HP + HM;  N = HH; break;
        default: W = Wb; wt = HP + HB;  N = DD; break;
    }
    const int h0 = blockIdx.x * 64;
    if (h0 >= N) return;
    const int d0 = blockIdx.y * 64;
    const int t = threadIdx.x;

    __shared__ __half tile[64][66];
#pragma unroll
    for (int i = 0; i < 16; i++) {
        int idx = i * 256 + t;
        int dr = idx >> 6, hc = idx & 63;
        tile[hc][dr] = __float2half_rn(W[(size_t)(d0 + dr) * N + h0 + hc]);
    }
    __syncthreads();
#pragma unroll
    for (int i = 0; i < 16; i++) {
        int idx = i * 256 + t;
        int hr = idx >> 6, dc = idx & 63;
        wt[(size_t)(h0 + hr) * DD + d0 + dc] = tile[hr][dc];
    }
}

// ---------------------------------------------------------------------------
// Remaining prep: x converts + w1v
// ---------------------------------------------------------------------------
__global__ void prep_rest(
    const float* __restrict__ x0, const float* __restrict__ x1,
    const float* __restrict__ Wp1, const float* __restrict__ vp,
    __half* __restrict__ HP, float* __restrict__ w1v)
{
    const int task = blockIdx.y;
    const int bx = blockIdx.x;
    const int tid = threadIdx.x;

    if (task < 2) {
        const float* x = (task == 0) ? x0 : x1;
        __half* xh = HP + ((task == 0) ? HX0 : HX1);
        int i = bx * 1024 + tid * 4;
        float4 v = *(const float4*)(x + i);
        __half2* o = (__half2*)(xh + i);
        o[0] = __floats2half2_rn(v.x, v.y);
        o[1] = __floats2half2_rn(v.z, v.w);
    } else {
        if (bx >= 256) return;
        int j = bx * 8 + (tid >> 5);
        int lane = tid & 31;
        const float* r = Wp1 + (size_t)j * HH;
        float acc = 0.0f;
#pragma unroll
        for (int h = lane; h < HH; h += 32) acc += r[h] * vp[h];
#pragma unroll
        for (int o = 16; o; o >>= 1) acc += __shfl_xor_sync(0xffffffffu, acc, o);
        if (lane == 0) w1v[j] = acc;
    }
}

// ---------------------------------------------------------------------------
// mma.sync fp16 dot-attention scores — R6 best-measured variant (unchanged).
// ---------------------------------------------------------------------------
#define MOFF_Y  0
#define MOFF_V  4096
#define MOFF_S  5120
#define MOFF_A  8192
#define MOFF_B  40960
#define MSMEM   106496

__global__ __launch_bounds__(512, 1) void dot_scores_mma(
    const float* __restrict__ x0, const float* __restrict__ x1,
    const __half* __restrict__ w1t, const __half* __restrict__ w2t,
    const float* __restrict__ vd1, const float* __restrict__ vd2,
    float* __restrict__ sp1, float* __restrict__ sp2)
{
    extern __shared__ char smc[];
    const uint32_t sb = smem_u32(smc);

    const int hc  = blockIdx.x;
    const int m   = blockIdx.y;
    const int att = blockIdx.z & 1;
    const int b   = blockIdx.z >> 1;

    const float* x = att ? x1 : x0;
    const float* y = att ? x0 : x1;
    const __half* wt = att ? w2t : w1t;
    const float* v = att ? vd2 : vd1;
    float* spart = att ? sp2 : sp1;

    const int t = threadIdx.x;
    const int lane = t & 31, wid = t >> 5;
    const int wn = wid & 3, whi = wid >> 2;
    const int lane15 = lane & 15, lhalf = lane >> 4;

    float* ysm = (float*)(smc + MOFF_Y);
    float* vsm = (float*)(smc + MOFF_V);
    float* ssm = (float*)(smc + MOFF_S);

    ((float2*)ysm)[t] = ((const float2*)(y + ((size_t)b * NN + m) * DD))[t];
    if (t < 64) ((float4*)vsm)[t] = ((const float4*)(v + hc * 256))[t];
    if (t < 128) ssm[t] = 0.0f;

    const float* xg = x + (size_t)b * NN * DD;
    const __half* wg = wt + (size_t)(hc * 256) * DD;

    const int an = t >> 2, ac = t & 3;
    const uint32_t a_st0 = sw128(an, ac);
    const uint32_t a_st1 = sw128(an, ac + 4);
    const int br = t >> 1, bc4 = (t & 1) * 4;
    uint32_t b_st[4];
#pragma unroll
    for (int j = 0; j < 4; j++) b_st[j] = sw128(br, bc4 + j);

    float xs[16];

#define ISSUE_B(kt, buf) do { \
        const __half* bp_ = wg + (size_t)br * DD + (kt) * 64 + bc4 * 8; \
        uint32_t Bb_ = sb + MOFF_B + (buf) * 32768u; \
        CP_ASYNC16(Bb_ + b_st[0], bp_); \
        CP_ASYNC16(Bb_ + b_st[1], bp_ + 8); \
        CP_ASYNC16(Bb_ + b_st[2], bp_ + 16); \
        CP_ASYNC16(Bb_ + b_st[3], bp_ + 24); \
        CP_COMMIT(); \
    } while (0)

#define LOAD_X(kt) do { \
        const float* xp_ = xg + (size_t)an * DD + (kt) * 64 + ac * 8; \
        *(float4*)&xs[0]  = *(const float4*)xp_; \
        *(float4*)&xs[4]  = *(const float4*)(xp_ + 4); \
        *(float4*)&xs[8]  = *(const float4*)(xp_ + 32); \
        *(float4*)&xs[12] = *(const float4*)(xp_ + 36); \
    } while (0)

#define STORE_A(kt, buf) do { \
        int kb_ = (kt) * 64 + ac * 8; \
        union { __half h[8]; uint4 q; } u0_, u1_; \
        _Pragma("unroll") \
        for (int j_ = 0; j_ < 8; j_++) { \
            u0_.h[j_] = __float2half_rn(xs[j_]     * ysm[kb_ + j_]); \
            u1_.h[j_] = __float2half_rn(xs[j_ + 8] * ysm[kb_ + 32 + j_]); \
        } \
        char* Ab_ = smc + MOFF_A + (buf) * 16384; \
        *(uint4*)(Ab_ + a_st0) = u0_.q; \
        *(uint4*)(Ab_ + a_st1) = u1_.q; \
    } while (0)

    float acc[2][8][4];
#pragma unroll
    for (int i = 0; i < 2; i++)
#pragma unroll
        for (int j = 0; j < 8; j++)
#pragma unroll
            for (int k = 0; k < 4; k++) acc[i][j][k] = 0.0f;

    ISSUE_B(0, 0);
    LOAD_X(0);
    __syncthreads();
    STORE_A(0, 0);
    CP_WAIT0();
    __syncthreads();

    uint32_t a_row[2], b_row[4];
#pragma unroll
    for (int mi = 0; mi < 2; mi++) a_row[mi] = wn * 32 + mi * 16 + lane15;
#pragma unroll
    for (int nj = 0; nj < 4; nj++) b_row[nj] = whi * 64 + nj * 16 + lane15;

    for (int kt = 0; kt < 16; kt++) {
        const int buf = kt & 1;
        if (kt < 15) { ISSUE_B(kt + 1, buf ^ 1); LOAD_X(kt + 1); }

        const uint32_t Ah = sb + MOFF_A + buf * 16384u;
        const uint32_t Bh = sb + MOFF_B + buf * 32768u;

#pragma unroll
        for (int ks = 0; ks < 4; ks++) {
            const uint32_t cidx = ks * 2 + lhalf;
            uint32_t a[2][4], bb[4][4];
#pragma unroll
            for (int mi = 0; mi < 2; mi++)
                LDSM4(a[mi][0], a[mi][1], a[mi][2], a[mi][3], Ah + sw128(a_row[mi], cidx));
#pragma unroll
            for (int nj = 0; nj < 4; nj++)
                LDSM4(bb[nj][0], bb[nj][1], bb[nj][2], bb[nj][3], Bh + sw128(b_row[nj], cidx));
#pragma unroll
            for (int mi = 0; mi < 2; mi++)
#pragma unroll
                for (int nj = 0; nj < 4; nj++) {
                    MMA16816(acc[mi][nj*2+0], a[mi][0], a[mi][1], a[mi][2], a[mi][3], bb[nj][0], bb[nj][2]);
                    MMA16816(acc[mi][nj*2+1], a[mi][0], a[mi][1], a[mi][2], a[mi][3], bb[nj][1], bb[nj][3]);
                }
        }

        if (kt < 15) { STORE_A(kt + 1, buf ^ 1); CP_WAIT0(); }
        __syncthreads();
    }

    float rs[2][2] = {{0.0f, 0.0f}, {0.0f, 0.0f}};
#pragma unroll
    for (int mi = 0; mi < 2; mi++)
#pragma unroll
        for (int hj = 0; hj < 8; hj++) {
            int hcol = whi * 64 + hj * 8 + (lane & 3) * 2;
            float v0 = vsm[hcol], v1 = vsm[hcol + 1];
            rs[mi][0] += ftanh(acc[mi][hj][0]) * v0 + ftanh(acc[mi][hj][1]) * v1;
            rs[mi][1] += ftanh(acc[mi][hj][2]) * v0 + ftanh(acc[mi][hj][3]) * v1;
        }
#pragma unroll
    for (int o = 1; o <= 2; o <<= 1) {
        rs[0][0] += __shfl_xor_sync(0xffffffffu, rs[0][0], o);
        rs[0][1] += __shfl_xor_sync(0xffffffffu, rs[0][1], o);
        rs[1][0] += __shfl_xor_sync(0xffffffffu, rs[1][0], o);
        rs[1][1] += __shfl_xor_sync(0xffffffffu, rs[1][1], o);
    }
    if ((lane & 3) == 0) {
        int r = wn * 32 + (lane >> 2);
        atomicAdd(&ssm[r],      rs[0][0]);
        atomicAdd(&ssm[r + 8],  rs[0][1]);
        atomicAdd(&ssm[r + 16], rs[1][0]);
        atomicAdd(&ssm[r + 24], rs[1][1]);
    }
    __syncthreads();
    if (t < 128)
        spart[(((size_t)b * NN + m) * 2 + hc) * NN + t] = ssm[t];
#undef ISSUE_B
#undef LOAD_X
#undef STORE_A
}

// ---------------------------------------------------------------------------
// fp16 mma projections (fp16 outputs)
// ---------------------------------------------------------------------------
#define POFF_A 0
#define POFF_B 32768
#define PSMEM  65536

__global__ __launch_bounds__(256, 2) void proj_mma(
    const __half* __restrict__ xh0, const __half* __restrict__ xh1,
    __half* __restrict__ HP)
{
    const __half* A; const __half* W; __half* Ch; int N;
    switch (blockIdx.z) {
        case 0: A = xh0; W = HP + HC1; Ch = HP + HXC; N = HH; break;
        case 1: A = xh1; W = HP + HC2; Ch = HP + HYC; N = HH; break;
        case 2: A = xh0; W = HP + HM;  Ch = HP + HXM; N = HH; break;
        case 3: A = xh1; W = HP + HM;  Ch = HP + HYM; N = HH; break;
        default: A = xh0; W = HP + HB; Ch = HP + HXB; N = DD; break;
    }
    const int bn = blockIdx.x * 128;
    if (bn >= N) return;
    const int bm = blockIdx.y * 128;

    extern __shared__ char smc[];
    const uint32_t sb = smem_u32(smc);
    const int t = threadIdx.x, lane = t & 31, wid = t >> 5;
    const int wm = wid & 3, whn = wid >> 2;
    const int lane15 = lane & 15, lhalf = lane >> 4;

    const int r = t >> 1, cc4 = (t & 1) * 4;
    uint32_t st_off[4];
#pragma unroll
    for (int j = 0; j < 4; j++) st_off[j] = sw128(r, cc4 + j);
    const __half* ag = A + (size_t)(bm + r) * DD + cc4 * 8;
    const __half* wgp = W + (size_t)(bn + r) * DD + cc4 * 8;

#define P_ISSUE(kt, buf) do { \
        uint32_t Ab_ = sb + POFF_A + (buf) * 16384u; \
        uint32_t Bb_ = sb + POFF_B + (buf) * 16384u; \
        const __half* ap_ = ag + (kt) * 64; \
        const __half* bp_ = wgp + (kt) * 64; \
        _Pragma("unroll") \
        for (int j_ = 0; j_ < 4; j_++) { \
            CP_ASYNC16(Ab_ + st_off[j_], ap_ + j_ * 8); \
            CP_ASYNC16(Bb_ + st_off[j_], bp_ + j_ * 8); \
        } \
        CP_COMMIT(); \
    } while (0)

    float acc[2][8][4];
#pragma unroll
    for (int i = 0; i < 2; i++)
#pragma unroll
        for (int j = 0; j < 8; j++)
#pragma unroll
            for (int k = 0; k < 4; k++) acc[i][j][k] = 0.0f;

    P_ISSUE(0, 0);
    CP_WAIT0();
    __syncthreads();

    uint32_t a_row[2], b_row[4];
#pragma unroll
    for (int mi = 0; mi < 2; mi++) a_row[mi] = wm * 32 + mi * 16 + lane15;
#pragma unroll
    for (int nj = 0; nj < 4; nj++) b_row[nj] = whn * 64 + nj * 16 + lane15;

    for (int kt = 0; kt < 16; kt++) {
        const int buf = kt & 1;
        if (kt < 15) P_ISSUE(kt + 1, buf ^ 1);

        const uint32_t Ah = sb + POFF_A + buf * 16384u;
        const uint32_t Bh = sb + POFF_B + buf * 16384u;

#pragma unroll
        for (int ks = 0; ks < 4; ks++) {
            const uint32_t cidx = ks * 2 + lhalf;
            uint32_t a[2][4], bb[4][4];
#pragma unroll
            for (int mi = 0; mi < 2; mi++)
                LDSM4(a[mi][0], a[mi][1], a[mi][2], a[mi][3], Ah + sw128(a_row[mi], cidx));
#pragma unroll
            for (int nj = 0; nj < 4; nj++)
                LDSM4(bb[nj][0], bb[nj][1], bb[nj][2], bb[nj][3], Bh + sw128(b_row[nj], cidx));
#pragma unroll
            for (int mi = 0; mi < 2; mi++)
#pragma unroll
                for (int nj = 0; nj < 4; nj++) {
                    MMA16816(acc[mi][nj*2+0], a[mi][0], a[mi][1], a[mi][2], a[mi][3], bb[nj][0], bb[nj][2]);
                    MMA16816(acc[mi][nj*2+1], a[mi][0], a[mi][1], a[mi][2], a[mi][3], bb[nj][1], bb[nj][3]);
                }
        }

        CP_WAIT0();
        __syncthreads();
    }

#pragma unroll
    for (int mi = 0; mi < 2; mi++) {
        int row = bm + wm * 32 + mi * 16 + (lane >> 2);
#pragma unroll
        for (int nj8 = 0; nj8 < 8; nj8++) {
            int col = bn + whn * 64 + nj8 * 8 + (lane & 3) * 2;
            *(__half2*)&Ch[(size_t)row * N + col] =
                __floats2half2_rn(acc[mi][nj8][0], acc[mi][nj8][1]);
            *(__half2*)&Ch[(size_t)(row + 8) * N + col] =
                __floats2half2_rn(acc[mi][nj8][2], acc[mi][nj8][3]);
        }
    }
#undef P_ISSUE
}

// ---------------------------------------------------------------------------
// Bilinear scores on tensor cores: grid (2, BB), tile 128m x 64n.
// ---------------------------------------------------------------------------
#define BOFF_A 0
#define BOFF_B 32768
#define BSMEM  49152

__global__ __launch_bounds__(256, 2) void bilin_tc(
    const __half* __restrict__ xh1, const __half* __restrict__ xbh,
    float* __restrict__ sbuf)
{
    const int half_n = blockIdx.x;
    const int b = blockIdx.y;
    const __half* A = xh1 + (size_t)b * NN * DD;
    const __half* Bq = xbh + (size_t)b * NN * DD + (size_t)half_n * 64 * DD;

    extern __shared__ char smc[];
    const uint32_t sb = smem_u32(smc);
    const int t = threadIdx.x, lane = t & 31, wid = t >> 5;
    const int wm = wid & 3, whn = wid >> 2;
    const int lane15 = lane & 15, lhalf = lane >> 4;

    const int ra = t >> 1, ca4 = (t & 1) * 4;
    uint32_t a_off[4];
#pragma unroll
    for (int j = 0; j < 4; j++) a_off[j] = sw128(ra, ca4 + j);
    const __half* ag = A + (size_t)ra * DD + ca4 * 8;
    const int rb = t >> 2, cb2 = (t & 3) * 2;
    const uint32_t b_off0 = sw128(rb, cb2), b_off1 = sw128(rb, cb2 + 1);
    const __half* bg = Bq + (size_t)rb * DD + cb2 * 8;

#define BL_ISSUE(kt, buf) do { \
        uint32_t Ab_ = sb + BOFF_A + (buf) * 16384u; \
        uint32_t Bb_ = sb + BOFF_B + (buf) * 8192u; \
        const __half* ap_ = ag + (kt) * 64; \
        const __half* bp_ = bg + (kt) * 64; \
        _Pragma("unroll") \
        for (int j_ = 0; j_ < 4; j_++) CP_ASYNC16(Ab_ + a_off[j_], ap_ + j_ * 8); \
        CP_ASYNC16(Bb_ + b_off0, bp_); \
        CP_ASYNC16(Bb_ + b_off1, bp_ + 8); \
        CP_COMMIT(); \
    } while (0)

    float acc[2][4][4];
#pragma unroll
    for (int i = 0; i < 2; i++)
#pragma unroll
        for (int j = 0; j < 4; j++)
#pragma unroll
            for (int k = 0; k < 4; k++) acc[i][j][k] = 0.0f;

    BL_ISSUE(0, 0);
    CP_WAIT0();
    __syncthreads();

    uint32_t a_row[2], b_row[2];
#pragma unroll
    for (int mi = 0; mi < 2; mi++) a_row[mi] = wm * 32 + mi * 16 + lane15;
#pragma unroll
    for (int nj = 0; nj < 2; nj++) b_row[nj] = whn * 32 + nj * 16 + lane15;

    for (int kt = 0; kt < 16; kt++) {
        const int buf = kt & 1;
        if (kt < 15) BL_ISSUE(kt + 1, buf ^ 1);

        const uint32_t Ah = sb + BOFF_A + buf * 16384u;
        const uint32_t Bh = sb + BOFF_B + buf * 8192u;

#pragma unroll
        for (int ks = 0; ks < 4; ks++) {
            const uint32_t cidx = ks * 2 + lhalf;
            uint32_t a[2][4], bb[2][4];
#pragma unroll
            for (int mi = 0; mi < 2; mi++)
                LDSM4(a[mi][0], a[mi][1], a[mi][2], a[mi][3], Ah + sw128(a_row[mi], cidx));
#pragma unroll
            for (int nj = 0; nj < 2; nj++)
                LDSM4(bb[nj][0], bb[nj][1], bb[nj][2], bb[nj][3], Bh + sw128(b_row[nj], cidx));
#pragma unroll
            for (int mi = 0; mi < 2; mi++)
#pragma unroll
                for (int nj = 0; nj < 2; nj++) {
                    MMA16816(acc[mi][nj*2+0], a[mi][0], a[mi][1], a[mi][2], a[mi][3], bb[nj][0], bb[nj][2]);
                    MMA16816(acc[mi][nj*2+1], a[mi][0], a[mi][1], a[mi][2], a[mi][3], bb[nj][1], bb[nj][3]);
                }
        }

        CP_WAIT0();
        __syncthreads();
    }

#pragma unroll
    for (int mi = 0; mi < 2; mi++) {
        int row = wm * 32 + mi * 16 + (lane >> 2);
#pragma unroll
        for (int nj8 = 0; nj8 < 4; nj8++) {
            int col = half_n * 64 + whn * 32 + nj8 * 8 + (lane & 3) * 2;
            sbuf[((size_t)b * NN + row) * NN + col]         = acc[mi][nj8][0];
            sbuf[((size_t)b * NN + row) * NN + col + 1]     = acc[mi][nj8][1];
            sbuf[((size_t)b * NN + row + 8) * NN + col]     = acc[mi][nj8][2];
            sbuf[((size_t)b * NN + row + 8) * NN + col + 1] = acc[mi][nj8][3];
        }
    }
#undef BL_ISSUE
}

// ---------------------------------------------------------------------------
// Concat + minus scores, 4-m blocked, fp16 inputs
// ---------------------------------------------------------------------------
__global__ __launch_bounds__(256) void pair_scores4(
    const __half* __restrict__ HP,
    const float* __restrict__ vcv, const float* __restrict__ vmv,
    float* __restrict__ sc, float* __restrict__ smn)
{
    const int m0 = blockIdx.x * 4, b = blockIdx.y, z = blockIdx.z;
    const __half* p = HP + (z ? HXM : HXC);
    const __half* q = HP + (z ? HYM : HYC);
    const float* v = z ? vmv : vcv;
    float* s = z ? smn : sc;
    const float sign = z ? -1.0f : 1.0f;

    const int t = threadIdx.x, lane = t & 31, w = t >> 5;
    __shared__ float qs[4][HH], vs[HH];
    {
        uint4 qv = ((const uint4*)(q + ((size_t)b * NN + m0) * HH))[t];
        const __half2* h2 = (const __half2*)&qv;
        float* dst = &qs[0][0] + t * 8;
        float2 f0 = __half22float2(h2[0]), f1 = __half22float2(h2[1]);
        float2 f2 = __half22float2(h2[2]), f3 = __half22float2(h2[3]);
        dst[0] = f0.x; dst[1] = f0.y; dst[2] = f1.x; dst[3] = f1.y;
        dst[4] = f2.x; dst[5] = f2.y; dst[6] = f3.x; dst[7] = f3.y;
        if (t < 128) ((float4*)vs)[t] = ((const float4*)v)[t];
    }
    __syncthreads();

    const __half* pb = p + (size_t)b * NN * HH;
    for (int n = w; n < NN; n += 8) {
        const __half* pr = pb + (size_t)n * HH;
        float a0 = 0.0f, a1 = 0.0f, a2 = 0.0f, a3 = 0.0f;
#pragma unroll
        for (int h = 0; h < HH; h += 32) {
            int hh = h + lane;
            float pv = __half2float(pr[hh]), vv = vs[hh];
            a0 += vv * ftanh(fmaf(sign, qs[0][hh], pv));
            a1 += vv * ftanh(fmaf(sign, qs[1][hh], pv));
            a2 += vv * ftanh(fmaf(sign, qs[2][hh], pv));
            a3 += vv * ftanh(fmaf(sign, qs[3][hh], pv));
        }
#pragma unroll
        for (int o = 16; o; o >>= 1) {
            a0 += __shfl_xor_sync(0xffffffffu, a0, o);
            a1 += __shfl_xor_sync(0xffffffffu, a1, o);
            a2 += __shfl_xor_sync(0xffffffffu, a2, o);
            a3 += __shfl_xor_sync(0xffffffffu, a3, o);
        }
        if (lane == 0) {
            s[((size_t)b * NN + m0 + 0) * NN + n] = a0;
            s[((size_t)b * NN + m0 + 1) * NN + n] = a1;
            s[((size_t)b * NN + m0 + 2) * NN + n] = a2;
            s[((size_t)b * NN + m0 + 3) * NN + n] = a3;
        }
    }
}

// ---------------------------------------------------------------------------
// Fused: 20 softmaxes + weighted sums + max + agg_rep, 4 m's per CTA
// (R14-measured best variant).
// ---------------------------------------------------------------------------
__global__ __launch_bounds__(256) void fuse_att4(
    const float* __restrict__ sc,  const float* __restrict__ sb,
    const float* __restrict__ smn, const float* __restrict__ sd1,
    const float* __restrict__ sd2,
    const float* __restrict__ x0,  const float* __restrict__ x1,
    float* __restrict__ aggrep)
{
    const int m0 = blockIdx.x * 4, b = blockIdx.y;
    const int t = threadIdx.x, lane = t & 31, w = t >> 5;
    __shared__ float aw[20][NN];

    if (t < 128) {
        const int n = t;
#pragma unroll
        for (int mi = 0; mi < 4; mi++) {
            const size_t bm = (size_t)b * NN + m0 + mi;
            aw[0 * 4 + mi][n] = sc [bm * NN + n];
            aw[1 * 4 + mi][n] = sb [bm * NN + n];
            aw[2 * 4 + mi][n] = smn[bm * NN + n];
            aw[3 * 4 + mi][n] = sd1[(bm * 2 + 0) * NN + n] + sd1[(bm * 2 + 1) * NN + n];
            aw[4 * 4 + mi][n] = sd2[(bm * 2 + 0) * NN + n] + sd2[(bm * 2 + 1) * NN + n];
        }
    }
    __syncthreads();

    for (int row = w; row < 20; row += 8) {
        float v0 = aw[row][lane], v1 = aw[row][lane + 32];
        float v2 = aw[row][lane + 64], v3 = aw[row][lane + 96];
        float mx = fmaxf(fmaxf(v0, v1), fmaxf(v2, v3));
#pragma unroll
        for (int o = 16; o; o >>= 1) mx = fmaxf(mx, __shfl_xor_sync(0xffffffffu, mx, o));
        float e0 = __expf(v0 - mx), e1 = __expf(v1 - mx);
        float e2 = __expf(v2 - mx), e3 = __expf(v3 - mx);
        float sm = e0 + e1 + e2 + e3;
#pragma unroll
        for (int o = 16; o; o >>= 1) sm += __shfl_xor_sync(0xffffffffu, sm, o);
        float inv = 1.0f / sm;
        aw[row][lane]      = e0 * inv; aw[row][lane + 32] = e1 * inv;
        aw[row][lane + 64] = e2 * inv; aw[row][lane + 96] = e3 * inv;
    }
    __syncthreads();

    const int d = t * 4;
    float4 acc[5][4];
#pragma unroll
    for (int a = 0; a < 5; a++)
#pragma unroll
        for (int mi = 0; mi < 4; mi++) acc[a][mi] = make_float4(0.f, 0.f, 0.f, 0.f);

    const float* x0b = x0 + (size_t)b * NN * DD;
    const float* x1b = x1 + (size_t)b * NN * DD;
    for (int n = 0; n < NN; n++) {
        float4 xv = *(const float4*)(x0b + (size_t)n * DD + d);
        float4 yv = *(const float4*)(x1b + (size_t)n * DD + d);
#pragma unroll
        for (int mi = 0; mi < 4; mi++) {
            float w0 = aw[0 * 4 + mi][n], w1 = aw[1 * 4 + mi][n];
            float w2 = aw[2 * 4 + mi][n], w3 = aw[3 * 4 + mi][n];
            float w4 = aw[4 * 4 + mi][n];
            acc[0][mi].x = fmaf(w0, xv.x, acc[0][mi].x); acc[0][mi].y = fmaf(w0, xv.y, acc[0][mi].y);
            acc[0][mi].z = fmaf(w0, xv.z, acc[0][mi].z); acc[0][mi].w = fmaf(w0, xv.w, acc[0][mi].w);
            acc[1][mi].x = fmaf(w1, xv.x, acc[1][mi].x); acc[1][mi].y = fmaf(w1, xv.y, acc[1][mi].y);
            acc[1][mi].z = fmaf(w1, xv.z, acc[1][mi].z); acc[1][mi].w = fmaf(w1, xv.w, acc[1][mi].w);
            acc[2][mi].x = fmaf(w2, xv.x, acc[2][mi].x); acc[2][mi].y = fmaf(w2, xv.y, acc[2][mi].y);
            acc[2][mi].z = fmaf(w2, xv.z, acc[2][mi].z); acc[2][mi].w = fmaf(w2, xv.w, acc[2][mi].w);
            acc[3][mi].x = fmaf(w3, xv.x, acc[3][mi].x); acc[3][mi].y = fmaf(w3, xv.y, acc[3][mi].y);
            acc[3][mi].z = fmaf(w3, xv.z, acc[3][mi].z); acc[3][mi].w = fmaf(w3, xv.w, acc[3][mi].w);
            acc[4][mi].x = fmaf(w4, yv.x, acc[4][mi].x); acc[4][mi].y = fmaf(w4, yv.y, acc[4][mi].y);
            acc[4][mi].z = fmaf(w4, yv.z, acc[4][mi].z); acc[4][mi].w = fmaf(w4, yv.w, acc[4][mi].w);
        }
    }

#pragma unroll
    for (int mi = 0; mi < 4; mi++) {
        const size_t bm = (size_t)b * NN + m0 + mi;
        float4 xm1 = *(const float4*)(x1b + (size_t)(m0 + mi) * DD + d);
        float4 ag;
        ag.x = fmaxf(xm1.x, fmaxf(fmaxf(acc[3][mi].x, acc[0][mi].x),
                                  fmaxf(fmaxf(acc[4][mi].x, acc[1][mi].x), acc[2][mi].x)));
        ag.y = fmaxf(xm1.y, fmaxf(fmaxf(acc[3][mi].y, acc[0][mi].y),
                                  fmaxf(fmaxf(acc[4][mi].y, acc[1][mi].y), acc[2][mi].y)));
        ag.z = fmaxf(xm1.z, fmaxf(fmaxf(acc[3][mi].z, acc[0][mi].z),
                                  fmaxf(fmaxf(acc[4][mi].z, acc[1][mi].z), acc[2][mi].z)));
        ag.w = fmaxf(xm1.w, fmaxf(fmaxf(acc[3][mi].w, acc[0][mi].w),
                                  fmaxf(fmaxf(acc[4][mi].w, acc[1][mi].w), acc[2][mi].w)));
        float* arow = aggrep + bm * (2 * DD);
        *(float4*)(arow + d)      = xm1;
        *(float4*)(arow + DD + d) = ag;
    }
}

// ---------------------------------------------------------------------------
// Final head
// ---------------------------------------------------------------------------
__global__ __launch_bounds__(256) void final_kernel(
    const float* __restrict__ aggrep, const float* __restrict__ w1v,
    const float* __restrict__ Wpred,  const float* __restrict__ bpred,
    float* __restrict__ out)
{
    const int b = blockIdx.x;
    const int t = threadIdx.x, lane = t & 31, w = t >> 5;
    __shared__ float sp[NN];
    __shared__ float r0[8], r1[8];
    const float* ab = aggrep + (size_t)b * NN * (2 * DD);

    for (int mm = w; mm < NN; mm += 8) {
        const float* ar = ab + (size_t)mm * (2 * DD);
        float acc = 0.0f;
#pragma unroll
        for (int j = lane; j < 2 * DD; j += 32) acc += ar[j] * w1v[j];
#pragma unroll
        for (int o = 16; o; o >>= 1) acc += __shfl_xor_sync(0xffffffffu, acc, o);
        if (lane == 0) sp[mm] = acc;
    }
    __syncthreads();
    if (w == 0) {
        float v0 = sp[lane], v1 = sp[lane + 32], v2 = sp[lane + 64], v3 = sp[lane + 96];
        float mx = fmaxf(fmaxf(v0, v1), fmaxf(v2, v3));
#pragma unroll
        for (int o = 16; o; o >>= 1) mx = fmaxf(mx, __shfl_xor_sync(0xffffffffu, mx, o));
        float e0 = __expf(v0 - mx), e1 = __expf(v1 - mx);
        float e2 = __expf(v2 - mx), e3 = __expf(v3 - mx);
        float sm = e0 + e1 + e2 + e3;
#pragma unroll
        for (int o = 16; o; o >>= 1) sm += __shfl_xor_sync(0xffffffffu, sm, o);
        float inv = 1.0f / sm;
        sp[lane] = e0 * inv; sp[lane + 32] = e1 * inv;
        sp[lane + 64] = e2 * inv; sp[lane + 96] = e3 * inv;
    }
    __syncthreads();

    float rp[8];
#pragma unroll
    for (int k = 0; k < 8; k++) rp[k] = 0.0f;
    for (int mm = 0; mm < NN; mm++) {
        float wgt = sp[mm];
        const float* ar = ab + (size_t)mm * (2 * DD);
#pragma unroll
        for (int k = 0; k < 8; k++) rp[k] = fmaf(wgt, ar[t + k * 256], rp[k]);
    }
    float p0 = 0.0f, p1 = 0.0f;
#pragma unroll
    for (int k = 0; k < 8; k++) {
        int j = t + k * 256;
        p0 = fmaf(rp[k], Wpred[(size_t)j * 2 + 0], p0);
        p1 = fmaf(rp[k], Wpred[(size_t)j * 2 + 1], p1);
    }
#pragma unroll
    for (int o = 16; o; o >>= 1) {
        p0 += __shfl_xor_sync(0xffffffffu, p0, o);
        p1 += __shfl_xor_sync(0xffffffffu, p1, o);
    }
    if (lane == 0) { r0[w] = p0; r1[w] = p1; }
    __syncthreads();
    if (t == 0) {
        float s0 = 0.0f, s1 = 0.0f;
#pragma unroll
        for (int i = 0; i < 8; i++) { s0 += r0[i]; s1 += r1[i]; }
        out[b * 2 + 0] = fmaxf(s0 + bpred[0], 0.0f);
        out[b * 2 + 1] = fmaxf(s1 + bpred[1], 0.0f);
    }
}

// ---------------------------------------------------------------------------
extern "C" void kernel_launch(void* const* d_in, const int* in_sizes, int n_in,
                              void* d_out, int out_size)
{
    (void)in_sizes; (void)n_in; (void)out_size;
    float* S = nullptr;
    cudaGetSymbolAddress((void**)&S, g_scratch);
    __half* HP = nullptr;
    cudaGetSymbolAddress((void**)&HP, g_half);

    const float* x0    = (const float*)d_in[0];
    const float* x1    = (const float*)d_in[1];
    const float* Wc1   = (const float*)d_in[2];
    const float* Wc2   = (const float*)d_in[3];
    const float* vc    = (const float*)d_in[4];
    const float* Wb    = (const float*)d_in[5];
    const float* Wd1   = (const float*)d_in[6];
    const float* vd1   = (const float*)d_in[7];
    const float* Wd2   = (const float*)d_in[8];
    const float* vd2   = (const float*)d_in[9];
    const float* Wm    = (const float*)d_in[10];
    const float* vm    = (const float*)d_in[11];
    const float* Wp1   = (const float*)d_in[14];
    const float* vp    = (const float*)d_in[16];
    const float* Wpred = (const float*)d_in[17];
    const float* bpred = (const float*)d_in[18];
    float* out = (float*)d_out;

    static cudaStream_t s_dot = nullptr;
    static cudaEvent_t ev_wd = nullptr, ev_dot = nullptr;
    static bool attrs_set = false;
    if (!attrs_set) {
        cudaFuncSetAttribute(dot_scores_mma,
                             cudaFuncAttributeMaxDynamicSharedMemorySize, MSMEM);
        cudaFuncSetAttribute(proj_mma,
                             cudaFuncAttributeMaxDynamicSharedMemorySize, PSMEM);
        cudaFuncSetAttribute(bilin_tc,
                             cudaFuncAttributeMaxDynamicSharedMemorySize, BSMEM);
        cudaStreamCreateWithFlags(&s_dot, cudaStreamNonBlocking);
        cudaEventCreateWithFlags(&ev_wd, cudaEventDisableTiming);
        cudaEventCreateWithFlags(&ev_dot, cudaEventDisableTiming);
        attrs_set = true;
    }

    __half* w1t = HP + HW1;
    __half* w2t = HP + HW2;
    __half* xh0 = HP + HX0;
    __half* xh1 = HP + HX1;
    __half* xbh = HP + HXB;

    // Critical-path prep: ONLY the dot weights, then fork the dot immediately.
    wtrans_d<<<dim3(8, 16, 2), 256>>>(Wd1, Wd2, HP);
    cudaEventRecord(ev_wd, 0);
    cudaStreamWaitEvent(s_dot, ev_wd, 0);
    dot_scores_mma<<<dim3(2, NN, 2 * BB), 512, MSMEM, s_dot>>>(
        x0, x1, w1t, w2t, vd1, vd2, S + OFF_SD1, S + OFF_SD2);
    cudaEventRecord(ev_dot, s_dot);

    // Main stream: the rest of the prep + small kernels (all hidden under dot)
    wtrans_rest<<<dim3(16, 16, 4), 256>>>(Wc1, Wc2, Wm, Wb, HP);
    prep_rest<<<dim3(1024, 3), 256>>>(x0, x1, Wp1, vp, HP, S + OFF_W1V);
    proj_mma<<<dim3(8, 8, 5), 256, PSMEM>>>(xh0, xh1, HP);
    bilin_tc<<<dim3(2, BB), 256, BSMEM>>>(xh1, xbh, S + OFF_SB);
    pair_scores4<<<dim3(NN / 4, BB, 2), 256>>>(HP, vc, vm, S + OFF_SC, S + OFF_SMN);

    // Join + fused aggregation (4 m's per CTA, R14-best) + final head
    cudaStreamWaitEvent(0, ev_dot, 0);
    fuse_att4<<<dim3(NN / 4, BB), 256>>>(S + OFF_SC, S + OFF_SB, S + OFF_SMN,
                                         S + OFF_SD1, S + OFF_SD2, x0, x1, S + OFF_AGG);
    final_kernel<<<BB, 256>>>(S + OFF_AGG, S + OFF_W1V, Wpred, bpred, out);
}